// round 12
// baseline (speedup 1.0000x reference)
#include <cuda_runtime.h>

#define NNODES 100000
#define NEDGES 3200000
#define DIN 64
#define HID 16
#define CAP 96                 // padded CSR bin size; P(deg>=96)~1e-18 for Poisson(32)
#define AGG_BLOCKS 1000

// ---------------- device scratch (no allocations allowed) -------------------
__device__ __align__(256) float g_p1[NNODES * HID];     // x@W1x + b_msg1
__device__ __align__(256) float g_s1[NNODES * HID];     // x@W_skip1 + b_skip1
__device__ __align__(256) float g_p2[NNODES * HID];     // h@W2x + b_msg2
__device__ __align__(256) float g_s2[NNODES * HID];     // h@W_skip2 + b_skip2
__device__ __align__(256) float g_acce[NNODES * HID];   // per-node sum of edge_attr
__device__ __align__(256) unsigned g_cur[NNODES];       // degree counters / counts
__device__ __align__(256) unsigned g_srcs[NNODES * CAP];// padded CSR of src ids

__device__ __forceinline__ void red_v4(float* addr, float4 v) {
    asm volatile("red.global.add.v4.f32 [%0], {%1,%2,%3,%4};"
                 :: "l"(addr), "f"(v.x), "f"(v.y), "f"(v.z), "f"(v.w)
                 : "memory");
}

// ---------------------------------------------------------------------------
// K1: zero g_acce (6.4 MB) + g_cur
// ---------------------------------------------------------------------------
__global__ __launch_bounds__(256) void k_zero() {
    int i = blockIdx.x * blockDim.x + threadIdx.x;
    const int nacc = NNODES * 4;                       // g_acce as float4
    if (i < nacc) reinterpret_cast<float4*>(g_acce)[i] = make_float4(0.f, 0.f, 0.f, 0.f);
    else if (i < nacc + NNODES) g_cur[i - nacc] = 0u;
}

// ---------------------------------------------------------------------------
// K2: per-node p1 = x@W1x + b_msg1 ; s1 = x@W_skip1 + b_skip1
// ---------------------------------------------------------------------------
__global__ __launch_bounds__(256) void k_node1(
    const float* __restrict__ x,
    const float* __restrict__ Wm1, const float* __restrict__ bm1,
    const float* __restrict__ Ws1, const float* __restrict__ bs1)
{
    __shared__ float sWx[DIN * HID];
    __shared__ float sWs[DIN * HID];
    __shared__ float sx[16][DIN];
    int t = threadIdx.x;
    for (int i = t; i < DIN * HID; i += 256) { sWx[i] = Wm1[i]; sWs[i] = Ws1[i]; }
    int ln = t >> 4, j = t & 15;
    int v = blockIdx.x * 16 + ln;
    if (v < NNODES) {
        reinterpret_cast<float4*>(sx[ln])[j] =
            reinterpret_cast<const float4*>(x + (size_t)v * DIN)[j];
    }
    __syncthreads();
    if (v >= NNODES) return;
    float ap = bm1[j], as = bs1[j];
    #pragma unroll
    for (int k = 0; k < DIN; k++) {
        float xv = sx[ln][k];
        ap = fmaf(xv, sWx[k * HID + j], ap);
        as = fmaf(xv, sWs[k * HID + j], as);
    }
    g_p1[(size_t)v * HID + j] = ap;
    g_s1[(size_t)v * HID + j] = as;
}

// ---------------------------------------------------------------------------
// K3: streaming ea scatter — acc_e[dst] += edge_attr[e] (measured ~50us)
// ---------------------------------------------------------------------------
__global__ __launch_bounds__(256) void k_edge_ea(const int* __restrict__ dst,
                                                 const float* __restrict__ ea) {
    int tid = blockIdx.x * blockDim.x + threadIdx.x;
    if (tid >= NEDGES * 4) return;
    int i = tid >> 2, c = tid & 3;
    float4 e = reinterpret_cast<const float4*>(ea)[tid];   // coalesced stream
    int d = __ldg(dst + i);
    red_v4(g_acce + (size_t)d * HID + c * 4, e);
}

// ---------------------------------------------------------------------------
// K4 (PROFILED SLOT): padded-CSR scatter, 4 edges/thread — no hist, no scan
// ---------------------------------------------------------------------------
__global__ __launch_bounds__(256) void k_scatter(const int* __restrict__ src,
                                                 const int* __restrict__ dst) {
    int i = blockIdx.x * blockDim.x + threadIdx.x;     // i < NEDGES/4 exactly
    int4 d4 = __ldg(reinterpret_cast<const int4*>(dst) + i);
    int4 s4 = __ldg(reinterpret_cast<const int4*>(src) + i);
    unsigned q0 = atomicAdd(&g_cur[d4.x], 1u);
    unsigned q1 = atomicAdd(&g_cur[d4.y], 1u);
    unsigned q2 = atomicAdd(&g_cur[d4.z], 1u);
    unsigned q3 = atomicAdd(&g_cur[d4.w], 1u);
    g_srcs[(unsigned)d4.x * CAP + q0] = (unsigned)s4.x;
    g_srcs[(unsigned)d4.y * CAP + q1] = (unsigned)s4.y;
    g_srcs[(unsigned)d4.z * CAP + q2] = (unsigned)s4.z;
    g_srcs[(unsigned)d4.w * CAP + q3] = (unsigned)s4.w;
}

// ---------------------------------------------------------------------------
// Warp gather: 32 indices in one coalesced LDG, shuffle-broadcast to 8
// 4-lane chunk groups; 4 independent row gathers in flight per lane.
// ---------------------------------------------------------------------------
__device__ __forceinline__ float4 gather_sum(const float* __restrict__ tbl,
                                             unsigned base0, unsigned cnt,
                                             int g, int c, int lane)
{
    float4 acc = make_float4(0.f, 0.f, 0.f, 0.f);
    for (unsigned base = 0; base < cnt; base += 32) {
        unsigned myi = base + (unsigned)lane;
        unsigned sidx = (myi < cnt) ? __ldg(g_srcs + base0 + myi) : 0xFFFFFFFFu;
        #pragma unroll
        for (int r = 0; r < 4; r++) {
            unsigned e = __shfl_sync(0xFFFFFFFFu, sidx, g + r * 8);
            if (e != 0xFFFFFFFFu) {
                float4 q = __ldg(reinterpret_cast<const float4*>(tbl + (size_t)e * HID) + c);
                acc.x += q.x; acc.y += q.y; acc.z += q.z; acc.w += q.w;
            }
        }
    }
    return acc;
}

// ---------------------------------------------------------------------------
// K5: PERSISTENT conv1 aggregate + warp-private node math.
//   Weights loaded once per block; each warp loops over nodes; no block sync
//   inside the loop.
// ---------------------------------------------------------------------------
__global__ __launch_bounds__(256) void k_agg1(
    const float* __restrict__ Wm1,
    const float* __restrict__ Wm2, const float* __restrict__ bm2,
    const float* __restrict__ Ws2, const float* __restrict__ bs2)
{
    __shared__ float sWe1[HID * HID], sW2x[HID * HID], sWs2[HID * HID];
    __shared__ float sb2[HID], sbs2[HID];
    __shared__ float accbuf[8][HID];
    int t = threadIdx.x;
    if (t < 256) { sWe1[t] = Wm1[DIN * HID + t]; sW2x[t] = Wm2[t]; sWs2[t] = Ws2[t]; }
    if (t < HID) { sb2[t] = bm2[t]; sbs2[t] = bs2[t]; }
    __syncthreads();

    int w = t >> 5, lane = t & 31;
    int g = lane >> 2, c = lane & 3;
    int j = lane & 15;

    for (int v = blockIdx.x * 8 + w; v < NNODES; v += AGG_BLOCKS * 8) {
        unsigned cnt = g_cur[v];
        float4 ap = gather_sum(g_p1, (unsigned)v * CAP, cnt, g, c, lane);
        #pragma unroll
        for (int m = 4; m <= 16; m <<= 1) {
            ap.x += __shfl_xor_sync(~0u, ap.x, m);
            ap.y += __shfl_xor_sync(~0u, ap.y, m);
            ap.z += __shfl_xor_sync(~0u, ap.z, m);
            ap.w += __shfl_xor_sync(~0u, ap.w, m);
        }
        if (lane < 4) reinterpret_cast<float4*>(accbuf[w])[lane] = ap;
        __syncwarp();

        float accp_j = accbuf[w][j];
        float acce_j = g_acce[(size_t)v * HID + j];
        float s1_j   = g_s1[(size_t)v * HID + j];
        float h = accp_j + s1_j;
        #pragma unroll
        for (int k = 0; k < HID; k++) {
            float ak = __shfl_sync(0xFFFFFFFFu, acce_j, k);
            h = fmaf(ak, sWe1[k * HID + j], h);
        }
        h = fmaxf(h, 0.f);
        float pv = sb2[j], sv = sbs2[j];
        #pragma unroll
        for (int k = 0; k < HID; k++) {
            float hk = __shfl_sync(0xFFFFFFFFu, h, k);
            pv = fmaf(hk, sW2x[k * HID + j], pv);
            sv = fmaf(hk, sWs2[k * HID + j], sv);
        }
        if (lane < HID) {
            g_p2[(size_t)v * HID + j] = pv;
            g_s2[(size_t)v * HID + j] = sv;
        }
        __syncwarp();
    }
}

// ---------------------------------------------------------------------------
// K6: PERSISTENT conv2 aggregate + fused final projection (warp-private)
// ---------------------------------------------------------------------------
__global__ __launch_bounds__(256) void k_agg2(
    const float* __restrict__ Wm2,
    const float* __restrict__ Wl3, const float* __restrict__ bl3,
    float* __restrict__ out)
{
    __shared__ float sWe2[HID * HID];
    __shared__ float sWl[HID * DIN];
    __shared__ float sbl[DIN];
    __shared__ float accbuf[8][HID];
    int t = threadIdx.x;
    if (t < 256) sWe2[t] = Wm2[HID * HID + t];
    for (int i = t; i < HID * DIN; i += 256) sWl[i] = Wl3[i];
    if (t < DIN) sbl[t] = bl3[t];
    __syncthreads();

    int w = t >> 5, lane = t & 31;
    int g = lane >> 2, c = lane & 3;
    int j = lane & 15;

    for (int v = blockIdx.x * 8 + w; v < NNODES; v += AGG_BLOCKS * 8) {
        unsigned cnt = g_cur[v];
        float4 ap = gather_sum(g_p2, (unsigned)v * CAP, cnt, g, c, lane);
        #pragma unroll
        for (int m = 4; m <= 16; m <<= 1) {
            ap.x += __shfl_xor_sync(~0u, ap.x, m);
            ap.y += __shfl_xor_sync(~0u, ap.y, m);
            ap.z += __shfl_xor_sync(~0u, ap.z, m);
            ap.w += __shfl_xor_sync(~0u, ap.w, m);
        }
        if (lane < 4) reinterpret_cast<float4*>(accbuf[w])[lane] = ap;
        __syncwarp();

        float accp_j = accbuf[w][j];
        float acce_j = g_acce[(size_t)v * HID + j];
        float s2_j   = g_s2[(size_t)v * HID + j];
        float h2 = accp_j + s2_j;
        #pragma unroll
        for (int k = 0; k < HID; k++) {
            float ak = __shfl_sync(0xFFFFFFFFu, acce_j, k);
            h2 = fmaf(ak, sWe2[k * HID + j], h2);
        }
        // final projection: each lane produces cols lane and lane+32
        int col0 = lane, col1 = lane + 32;
        float o0 = sbl[col0], o1 = sbl[col1];
        #pragma unroll
        for (int k = 0; k < HID; k++) {
            float hk = __shfl_sync(0xFFFFFFFFu, h2, k);
            o0 = fmaf(hk, sWl[k * DIN + col0], o0);
            o1 = fmaf(hk, sWl[k * DIN + col1], o1);
        }
        out[(size_t)v * DIN + col0] = o0;
        out[(size_t)v * DIN + col1] = o1;
        __syncwarp();
    }
}

// ---------------------------------------------------------------------------
extern "C" void kernel_launch(void* const* d_in, const int* in_sizes, int n_in,
                              void* d_out, int out_size)
{
    const float* x   = (const float*)d_in[0];
    const int*   ei  = (const int*)  d_in[1];
    const float* ea  = (const float*)d_in[2];
    const float* Wm1 = (const float*)d_in[3];
    const float* bm1 = (const float*)d_in[4];
    const float* Ws1 = (const float*)d_in[5];
    const float* bs1 = (const float*)d_in[6];
    const float* Wm2 = (const float*)d_in[7];
    const float* bm2 = (const float*)d_in[8];
    const float* Ws2 = (const float*)d_in[9];
    const float* bs2 = (const float*)d_in[10];
    const float* Wl3 = (const float*)d_in[11];
    const float* bl3 = (const float*)d_in[12];
    const int* src = ei;
    const int* dst = ei + NEDGES;
    float* out = (float*)d_out;

    // Slot 4 (profiled) = k_scatter (new padded variant).
    k_zero   <<<(NNODES * 5 + 255) / 256, 256>>>();
    k_node1  <<<(NNODES + 15) / 16, 256>>>(x, Wm1, bm1, Ws1, bs1);
    k_edge_ea<<<(NEDGES * 4 + 255) / 256, 256>>>(dst, ea);
    k_scatter<<<NEDGES / 4 / 256, 256>>>(src, dst);
    k_agg1   <<<AGG_BLOCKS, 256>>>(Wm1, Wm2, bm2, Ws2, bs2);
    k_agg2   <<<AGG_BLOCKS, 256>>>(Wm2, Wl3, bl3, out);
}